// round 4
// baseline (speedup 1.0000x reference)
#include <cuda_runtime.h>
#include <cuda_bf16.h>
#include <math.h>
#include <stdint.h>

#define BB 1024
#define DD 64
#define HH 128
#define NKS 4          // K=64 -> 4 k-steps of 16 (bf16 mma)
#define JT 32          // j-tile
#define IB 2           // i's per CTA
#define NBLK (BB / JT) // 32 j-blocks
#define ASTR 36        // A smem row stride in u32 words (32 + pad)
#define TSTR 132       // T1/T2 smem row stride (words)

// Scratch (allocation-free rule: __device__ globals)
__device__ __align__(16) float g_T1[BB * HH];
__device__ __align__(16) float g_T2[BB * HH];
__device__ __align__(16) float g_S[BB * HH];
__device__ float g_tau[BB];

__device__ __forceinline__ uint32_t pack_bf2(float lo, float hi) {
  __nv_bfloat162 v = __floats2bfloat162_rn(lo, hi);
  return *(uint32_t*)&v;
}

__device__ __forceinline__ void mma16(float* c, uint32_t a0, uint32_t a1,
                                      uint32_t a2, uint32_t a3, uint32_t b0,
                                      uint32_t b1) {
  asm volatile(
      "mma.sync.aligned.m16n8k16.row.col.f32.bf16.bf16.f32 "
      "{%0,%1,%2,%3},{%4,%5,%6,%7},{%8,%9},{%0,%1,%2,%3};"
      : "+f"(c[0]), "+f"(c[1]), "+f"(c[2]), "+f"(c[3])
      : "r"(a0), "r"(a1), "r"(a2), "r"(a3), "r"(b0), "r"(b1));
}

// ---------------------------------------------------------------------------
// Kernel 1: per-row precompute + zero g_S
//   T1[i,h] = x_i@(Wi+Wd) + b1   T2[j,h] = x_j@(Wj-Wd)   tau[i]
// ---------------------------------------------------------------------------
__global__ __launch_bounds__(HH) void precompute_kernel(
    const float* __restrict__ x, const float* __restrict__ W1,
    const float* __restrict__ b1, const float* __restrict__ Wt,
    const float* __restrict__ bt) {
  __shared__ float xi[DD];
  const int i = blockIdx.x;
  const int h = threadIdx.x;
  if (h < DD) xi[h] = x[i * DD + h];
  g_S[i * HH + h] = 0.f;
  __syncthreads();

  float ai = 0.f, aj = 0.f, ad = 0.f;
#pragma unroll 8
  for (int d = 0; d < DD; ++d) {
    const float xv = xi[d];
    ai += xv * W1[d * HH + h];
    aj += xv * W1[(DD + d) * HH + h];
    ad += xv * W1[(2 * DD + d) * HH + h];
  }
  g_T1[i * HH + h] = ai + ad + b1[h];
  g_T2[i * HH + h] = aj - ad;

  if (h == 0) {
    float z = bt[0];
#pragma unroll 8
    for (int d = 0; d < DD; ++d) z += xi[d] * Wt[d];
    const float sp = (z > 20.f) ? z : log1pf(expf(z));
    g_tau[i] = fmaxf(sp, 0.01f) + 1.0f;
  }
}

// ---------------------------------------------------------------------------
// Kernel 2: symmetric bf16 pair-GEMM. CTA c: i-pair p=c>>1 (i0=2p), j-half
// c&1. j-tiles ti = b+half, b+half+2, ..., 31 where b = i0>>5 (own block).
// Normal orientation -> register sacc (flushed via atomicAdd at end).
// Transpose orientation (ti != b) -> atomicAdd to g_S[j] per tile.
// ---------------------------------------------------------------------------
__global__ __launch_bounds__(256, 2) void pair_kernel(
    const float* __restrict__ x, const float* __restrict__ W1) {
  __shared__ __align__(16) float xs[IB][DD];
  __shared__ __align__(16) float xjs[JT * DD];
  __shared__ __align__(16) uint32_t As[IB][JT * ASTR];  // bf16x2 packed
  __shared__ __align__(16) float t2s[JT * TSTR];
  __shared__ __align__(16) float t1s[JT * TSTR];

  const int t = threadIdx.x;
  const int w = t >> 5, lane = t & 31;
  const int wr = w >> 2, wc = w & 3;
  const int g = lane >> 2, tig = lane & 3;
  const int p = blockIdx.x >> 1;
  const int half = blockIdx.x & 1;
  const int i0 = p * IB;
  const int b = i0 >> 5;  // own j-block

  if (t < IB * DD) ((float*)xs)[t] = x[(size_t)i0 * DD + t];

  // B fragments (Wab) -> bf16x2 registers.
  uint32_t Bv[NKS][4][2];
#pragma unroll
  for (int ks = 0; ks < NKS; ks++)
#pragma unroll
    for (int nt = 0; nt < 4; nt++) {
      const int n = wc * 32 + nt * 8 + g;
#pragma unroll
      for (int hf = 0; hf < 2; hf++) {
        const int k = ks * 16 + 2 * tig + hf * 8;
        Bv[ks][nt][hf] = pack_bf2(W1[(size_t)(3 * DD + k) * HH + n],
                                  W1[(size_t)(3 * DD + k + 1) * HH + n]);
      }
    }

  // Per-i T1 (normal epilogue) and T2 (transpose epilogue), fp32 registers
  float2 t1iv[IB][4], t2iv[IB][4];
#pragma unroll
  for (int ii = 0; ii < IB; ii++)
#pragma unroll
    for (int nt = 0; nt < 4; nt++) {
      const size_t off = (size_t)(i0 + ii) * HH + wc * 32 + nt * 8 + 2 * tig;
      t1iv[ii][nt] = *(const float2*)&g_T1[off];
      t2iv[ii][nt] = *(const float2*)&g_T2[off];
    }

  float sacc[IB][8];
#pragma unroll
  for (int a = 0; a < IB; a++)
#pragma unroll
    for (int q = 0; q < 8; q++) sacc[a][q] = 0.f;

  const int ar = wr * 16 + g;  // local j row for c0/c1 (c2/c3: +8)

  for (int ti = b + half; ti < NBLK; ti += 2) {
    const int j0 = ti * JT;
    const bool diag = (ti == b);
    __syncthreads();  // previous tile's smem reads done
    // stage x_j (32x64), T2_j (32x128), T1_j (32x128, off-diagonal only)
#pragma unroll
    for (int r = 0; r < 2; r++) {
      const int e = t + r * 256;
      const int j = e >> 4, q = (e & 15) << 2;
      *(float4*)&xjs[j * DD + q] = *(const float4*)&x[(size_t)(j0 + j) * DD + q];
    }
#pragma unroll
    for (int r = 0; r < 4; r++) {
      const int e = t + r * 256;
      const int j = e >> 5, q = (e & 31) << 2;
      *(float4*)&t2s[j * TSTR + q] =
          *(const float4*)&g_T2[(size_t)(j0 + j) * HH + q];
    }
    if (!diag) {
#pragma unroll
      for (int r = 0; r < 4; r++) {
        const int e = t + r * 256;
        const int j = e >> 5, q = (e & 31) << 2;
        *(float4*)&t1s[j * TSTR + q] =
            *(const float4*)&g_T1[(size_t)(j0 + j) * HH + q];
      }
    }
    __syncthreads();

    // Build both A tiles (bf16 |x_i - x_j|)
#pragma unroll
    for (int ii = 0; ii < IB; ii++) {
#pragma unroll
      for (int r = 0; r < 2; r++) {
        const int e = t + r * 256;
        const int row = e >> 4, cg = e & 15;
        const float4 xj4 = *(const float4*)&xjs[row * DD + cg * 4];
        const float4 xi4 = *(const float4*)&xs[ii][cg * 4];
        uint2 o;
        o.x = pack_bf2(fabsf(xj4.x - xi4.x), fabsf(xj4.y - xi4.y));
        o.y = pack_bf2(fabsf(xj4.z - xi4.z), fabsf(xj4.w - xi4.w));
        *(uint2*)&As[ii][row * ASTR + cg * 2] = o;
      }
    }
    __syncthreads();

    float tracc[4][4];
#pragma unroll
    for (int nt = 0; nt < 4; nt++)
#pragma unroll
      for (int q = 0; q < 4; q++) tracc[nt][q] = 0.f;

#pragma unroll
    for (int ii = 0; ii < IB; ii++) {
      float cc[4][4];
#pragma unroll
      for (int nt = 0; nt < 4; nt++)
#pragma unroll
        for (int q = 0; q < 4; q++) cc[nt][q] = 0.f;

#pragma unroll
      for (int ks = 0; ks < NKS; ks++) {
        const uint32_t a0 = As[ii][ar * ASTR + ks * 8 + tig];
        const uint32_t a1 = As[ii][(ar + 8) * ASTR + ks * 8 + tig];
        const uint32_t a2 = As[ii][ar * ASTR + ks * 8 + tig + 4];
        const uint32_t a3 = As[ii][(ar + 8) * ASTR + ks * 8 + tig + 4];
#pragma unroll
        for (int nt = 0; nt < 4; nt++)
          mma16(cc[nt], a0, a1, a2, a3, Bv[ks][nt][0], Bv[ks][nt][1]);
      }

      // normal: S[i] += relu(D + T1[i] + T2[j])
#pragma unroll
      for (int nt = 0; nt < 4; nt++) {
        const int h0 = wc * 32 + nt * 8 + 2 * tig;
        const float2 ta = *(const float2*)&t2s[ar * TSTR + h0];
        const float2 tb = *(const float2*)&t2s[(ar + 8) * TSTR + h0];
        const float2 t1 = t1iv[ii][nt];
        sacc[ii][nt * 2 + 0] += fmaxf(cc[nt][0] + t1.x + ta.x, 0.f) +
                                fmaxf(cc[nt][2] + t1.x + tb.x, 0.f);
        sacc[ii][nt * 2 + 1] += fmaxf(cc[nt][1] + t1.y + ta.y, 0.f) +
                                fmaxf(cc[nt][3] + t1.y + tb.y, 0.f);
      }
      // transpose: S[j] += relu(D + T1[j] + T2[i])  (skip diagonal block)
      if (!diag) {
#pragma unroll
        for (int nt = 0; nt < 4; nt++) {
          const int h0 = wc * 32 + nt * 8 + 2 * tig;
          const float2 ja = *(const float2*)&t1s[ar * TSTR + h0];
          const float2 jb = *(const float2*)&t1s[(ar + 8) * TSTR + h0];
          const float2 t2 = t2iv[ii][nt];
          tracc[nt][0] += fmaxf(cc[nt][0] + ja.x + t2.x, 0.f);
          tracc[nt][1] += fmaxf(cc[nt][1] + ja.y + t2.y, 0.f);
          tracc[nt][2] += fmaxf(cc[nt][2] + jb.x + t2.x, 0.f);
          tracc[nt][3] += fmaxf(cc[nt][3] + jb.y + t2.y, 0.f);
        }
      }
    }

    if (!diag) {
#pragma unroll
      for (int nt = 0; nt < 4; nt++) {
        const int h0 = wc * 32 + nt * 8 + 2 * tig;
        atomicAdd(&g_S[(size_t)(j0 + ar) * HH + h0 + 0], tracc[nt][0]);
        atomicAdd(&g_S[(size_t)(j0 + ar) * HH + h0 + 1], tracc[nt][1]);
        atomicAdd(&g_S[(size_t)(j0 + ar + 8) * HH + h0 + 0], tracc[nt][2]);
        atomicAdd(&g_S[(size_t)(j0 + ar + 8) * HH + h0 + 1], tracc[nt][3]);
      }
    }
  }

  // Flush normal-orientation sacc: reduce over row-groups g, then atomicAdd.
#pragma unroll
  for (int a = 0; a < IB; a++)
#pragma unroll
    for (int q = 0; q < 8; q++) {
      float v = sacc[a][q];
      v += __shfl_xor_sync(0xffffffffu, v, 4);
      v += __shfl_xor_sync(0xffffffffu, v, 8);
      v += __shfl_xor_sync(0xffffffffu, v, 16);
      sacc[a][q] = v;
    }
  if (lane < 4) {  // g==0, tig==lane
#pragma unroll
    for (int a = 0; a < IB; a++)
#pragma unroll
      for (int nt = 0; nt < 4; nt++) {
        const int h0 = wc * 32 + nt * 8 + 2 * lane;
        atomicAdd(&g_S[(size_t)(i0 + a) * HH + h0 + 0], sacc[a][nt * 2 + 0]);
        atomicAdd(&g_S[(size_t)(i0 + a) * HH + h0 + 1], sacc[a][nt * 2 + 1]);
      }
  }
}

// ---------------------------------------------------------------------------
// Kernel 3: head + layernorm per row. 128 threads, 4 warps.
// ---------------------------------------------------------------------------
__global__ __launch_bounds__(HH) void head_kernel(
    const float* __restrict__ x, const float* __restrict__ W2,
    const float* __restrict__ b2, const float* __restrict__ Wa,
    const float* __restrict__ ba, const float* __restrict__ Wr,
    const float* __restrict__ br, const float* __restrict__ gamma,
    const float* __restrict__ beta, float* __restrict__ out) {
  __shared__ float S_s[HH], hm_s[HH], xi[DD];
  __shared__ float red[4];
  const int i = blockIdx.x;
  const int t = threadIdx.x;
  const int w = t >> 5, lane = t & 31;

  if (t < DD) xi[t] = x[i * DD + t];
  S_s[t] = g_S[(size_t)i * HH + t] * (1.0f / BB);
  __syncthreads();

  float acc = b2[t];
#pragma unroll 8
  for (int k = 0; k < HH; ++k) acc += S_s[k] * W2[k * HH + t];
  hm_s[t] = acc / g_tau[i];
  __syncthreads();

  float acc2 = ba[t];
#pragma unroll 8
  for (int k = 0; k < HH; ++k) acc2 += hm_s[k] * Wa[k * HH + t];
  const float hv = fmaxf(acc2, 0.f);
  float a3 = br[t];
#pragma unroll 8
  for (int d = 0; d < DD; ++d) a3 += xi[d] * Wr[d * HH + t];
  const float yv = hv + a3;

  float v = yv;
#pragma unroll
  for (int off = 16; off > 0; off >>= 1) v += __shfl_xor_sync(0xffffffffu, v, off);
  if (lane == 0) red[w] = v;
  __syncthreads();
  const float mu = (red[0] + red[1] + red[2] + red[3]) * (1.0f / HH);
  __syncthreads();
  const float dv = yv - mu;
  float v2 = dv * dv;
#pragma unroll
  for (int off = 16; off > 0; off >>= 1) v2 += __shfl_xor_sync(0xffffffffu, v2, off);
  if (lane == 0) red[w] = v2;
  __syncthreads();
  const float var = (red[0] + red[1] + red[2] + red[3]) * (1.0f / HH);

  out[(size_t)i * HH + t] = dv * rsqrtf(var + 1e-5f) * gamma[t] + beta[t];
}

// ---------------------------------------------------------------------------
// Inputs: 0:x 1:W1 2:b1 3:W2 4:b2 5:Wt 6:bt 7:Wa 8:ba 9:Wr 10:br 11:gamma 12:beta
// ---------------------------------------------------------------------------
extern "C" void kernel_launch(void* const* d_in, const int* in_sizes, int n_in,
                              void* d_out, int out_size) {
  const float* x     = (const float*)d_in[0];
  const float* W1    = (const float*)d_in[1];
  const float* b1    = (const float*)d_in[2];
  const float* W2    = (const float*)d_in[3];
  const float* b2    = (const float*)d_in[4];
  const float* Wt    = (const float*)d_in[5];
  const float* bt    = (const float*)d_in[6];
  const float* Wa    = (const float*)d_in[7];
  const float* ba    = (const float*)d_in[8];
  const float* Wr    = (const float*)d_in[9];
  const float* br    = (const float*)d_in[10];
  const float* gamma = (const float*)d_in[11];
  const float* beta  = (const float*)d_in[12];
  float* out = (float*)d_out;

  precompute_kernel<<<BB, HH>>>(x, W1, b1, Wt, bt);
  pair_kernel<<<BB, 256>>>(x, W1);
  head_kernel<<<BB, HH>>>(x, W2, b2, Wa, ba, Wr, br, gamma, beta, out);
}